// round 12
// baseline (speedup 1.0000x reference)
#include <cuda_runtime.h>
#include <cub/cub.cuh>
#include <cstdint>

#define MAXP 10
#define MAXV 160000
#define NCAP (1 << 21)
#define IDX_BITS 21
#define IDX_MASK ((1u << IDX_BITS) - 1u)

// Output layout (tuple order): voxels | coors | num_points | voxel_num
#define OFF_VOX   0
#define OFF_COORS 8000000
#define OFF_CNT   8480000
#define OFF_VNUM  8640000
#define OUT_ELEMS 8640001

struct MaxOp {
    __host__ __device__ __forceinline__ int operator()(int a, int b) const {
        return a > b ? a : b;
    }
};

// ---- device scratch (static globals: allowed; no runtime allocation) ----
__device__ unsigned int g_keys_in[NCAP];            // wrapped int32 key, sign-flipped
__device__ unsigned int g_keys_out[NCAP];
__device__ unsigned long long g_vals_in[NCAP];      // (lin << 21) | idx
__device__ unsigned long long g_vals_out[NCAP];
__device__ int g_fidx[NCAP];   // head flag scattered to ORIGINAL index order
__device__ int g_rank[NCAP];   // exclusive prefix sum of g_fidx
__device__ int g_w[NCAP];      // is_head ? p : -1   (sorted order)
__device__ int g_hp[NCAP];     // inclusive max-scan of g_w = head_pos (cummax)
__device__ int g_cnt[MAXV];
__device__ __align__(256) unsigned char g_cubtmp[96u << 20];

// IEEE f32 quantization (bit-matches XLA CPU float32 math; immune to fast-math).
__device__ __forceinline__ void grid_dims(const float* __restrict__ vs,
                                          const float* __restrict__ cr,
                                          int& gx, int& gy, int& gz) {
    gx = (int)rintf(__fdiv_rn(__fsub_rn(cr[3], cr[0]), vs[0]));
    gy = (int)rintf(__fdiv_rn(__fsub_rn(cr[4], cr[1]), vs[1]));
    gz = (int)rintf(__fdiv_rn(__fsub_rn(cr[5], cr[2]), vs[2]));
}

// Pass K: quantize; emulate the reference's INT32-WRAPPED sort key:
//   key = int32(lin * N + idx)   (jax_enable_x64=False coerces int64 -> int32)
// Sign-flip for unsigned radix order; payload carries (lin << 21 | idx).
__global__ void passK(const float* __restrict__ pts, const float* __restrict__ vs,
                      const float* __restrict__ cr, int n) {
    int i = blockIdx.x * 256 + threadIdx.x;
    if (i >= n) return;
    int gx, gy, gz;
    grid_dims(vs, cr, gx, gy, gz);
    float m0 = cr[0], m1 = cr[1], m2 = cr[2];
    size_t b = (size_t)i * 5;
    float px = pts[b + 0], py = pts[b + 1], pz = pts[b + 2];
    int cx = (int)floorf(__fdiv_rn(__fsub_rn(px, m0), vs[0]));
    int cy = (int)floorf(__fdiv_rn(__fsub_rn(py, m1), vs[1]));
    int cz = (int)floorf(__fdiv_rn(__fsub_rn(pz, m2), vs[2]));
    bool valid = (cx >= 0) && (cx < gx) && (cy >= 0) && (cy < gy) &&
                 (cz >= 0) && (cz < gz);
    int total = gx * gy * gz;                         // 82,944,000 fits int32
    int lin = valid ? ((cx * gy + cy) * gz + cz) : total;
    unsigned int wkey = (unsigned int)lin * (unsigned int)n + (unsigned int)i; // int32 wrap
    g_keys_in[i] = wkey ^ 0x80000000u;                // signed order -> unsigned order
    g_vals_in[i] = ((unsigned long long)(unsigned)lin << IDX_BITS) | (unsigned)i;
}

// Pass S1 (wrapped-sorted order): is_head = valid && lin != prev_lin;
// scatter head flag to original index order; head-position helper for cummax.
__global__ void passS1(const float* __restrict__ vs, const float* __restrict__ cr, int n) {
    int p = blockIdx.x * 256 + threadIdx.x;
    if (p >= n) return;
    int gx, gy, gz;
    grid_dims(vs, cr, gx, gy, gz);
    int total = gx * gy * gz;
    int lin  = (int)(g_vals_out[p] >> IDX_BITS);
    int linp = (p > 0) ? (int)(g_vals_out[p - 1] >> IDX_BITS) : -1;
    int is_head = (lin < total) && (lin != linp);
    g_w[p] = is_head ? p : -1;
    g_fidx[(unsigned)(g_vals_out[p] & IDX_MASK)] = is_head;
}

// Pass S2 (wrapped-sorted order): slot = p - head_pos; vox = rank of head's
// original index among heads; scatter kept points, coors at heads, counts.
__global__ void passS2(const float* __restrict__ pts, const float* __restrict__ vs,
                       const float* __restrict__ cr, int n, float* __restrict__ out) {
    int p = blockIdx.x * 256 + threadIdx.x;
    if (p >= n) return;
    int gx, gy, gz;
    grid_dims(vs, cr, gx, gy, gz);
    int total = gx * gy * gz;
    int lin = (int)(g_vals_out[p] >> IDX_BITS);
    if (lin >= total) return;                 // invalid point
    int h = g_hp[p];                          // position of this run's head
    int slot = p - h;                         // counts interleaved invalids too (as ref does)
    int head_orig = (int)(g_vals_out[h] & IDX_MASK);
    int vox = g_rank[head_orig];              // id = rank of head among heads by orig idx
    if (vox >= MAXV) return;
    atomicAdd(&g_cnt[vox], 1);                // uncapped; min(,10) applied in passT
    if (slot < MAXP) {
        int o = (int)(g_vals_out[p] & IDX_MASK);
        const float* src = pts + (size_t)o * 5;
        float* dst = out + OFF_VOX + (size_t)vox * (MAXP * 5) + slot * 5;
        dst[0] = src[0]; dst[1] = src[1]; dst[2] = src[2];
        dst[3] = src[3]; dst[4] = src[4];
    }
    if (p == h) {                             // head writes coors (z, y, x)
        int cz = lin % gz;
        int r = lin / gz;
        int cy = r % gy;
        int cx = r / gy;
        float* oc = out + OFF_COORS + (size_t)vox * 3;
        oc[0] = (float)cz;
        oc[1] = (float)cy;
        oc[2] = (float)cx;
    }
}

// Pass T: counts -> min(cnt,10) as float, voxel_num scalar.
__global__ void passT(float* __restrict__ out, int n) {
    int v = blockIdx.x * blockDim.x + threadIdx.x;
    if (v < MAXV) out[OFF_CNT + v] = (float)min(g_cnt[v], MAXP);
    if (v == 0) {
        int H = g_rank[n - 1] + g_fidx[n - 1];
        out[OFF_VNUM] = (float)min(H, MAXV);
    }
}

extern "C" void kernel_launch(void* const* d_in, const int* in_sizes, int n_in,
                              void* d_out, int out_size) {
    // Disambiguate inputs by element count: points = largest,
    // voxel_size = 3 elements, coors_range = 6 elements.
    const float* pts = nullptr;
    const float* vs  = nullptr;
    const float* cr  = nullptr;
    int pts_size = -1;
    for (int k = 0; k < n_in; k++) {
        int sz = in_sizes[k];
        if (sz == 3) vs = (const float*)d_in[k];
        else if (sz == 6) cr = (const float*)d_in[k];
        if (sz > pts_size) { pts_size = sz; pts = (const float*)d_in[k]; }
    }
    int n = pts_size / 5;
    float* out = (float*)d_out;

    void *p_kin, *p_kout, *p_vin, *p_vout, *p_fidx, *p_rank, *p_w, *p_hp, *p_cnt, *p_tmp;
    cudaGetSymbolAddress(&p_kin, g_keys_in);
    cudaGetSymbolAddress(&p_kout, g_keys_out);
    cudaGetSymbolAddress(&p_vin, g_vals_in);
    cudaGetSymbolAddress(&p_vout, g_vals_out);
    cudaGetSymbolAddress(&p_fidx, g_fidx);
    cudaGetSymbolAddress(&p_rank, g_rank);
    cudaGetSymbolAddress(&p_w, g_w);
    cudaGetSymbolAddress(&p_hp, g_hp);
    cudaGetSymbolAddress(&p_cnt, g_cnt);
    cudaGetSymbolAddress(&p_tmp, g_cubtmp);

    cudaMemsetAsync(out, 0, (size_t)OUT_ELEMS * sizeof(float), 0);
    cudaMemsetAsync(p_cnt, 0, sizeof(int) * MAXV, 0);

    int nb = (n + 255) / 256;
    passK<<<nb, 256>>>(pts, vs, cr, n);

    // Stable radix sort of 32-bit wrapped keys; stable tie-break reproduces
    // jnp.argsort(kind='stable') exactly (input is in original index order).
    size_t tb = sizeof(g_cubtmp);
    cub::DeviceRadixSort::SortPairs(p_tmp, tb,
                                    (const unsigned int*)p_kin,
                                    (unsigned int*)p_kout,
                                    (const unsigned long long*)p_vin,
                                    (unsigned long long*)p_vout,
                                    n, 0, 32, 0);

    passS1<<<nb, 256>>>(vs, cr, n);

    tb = sizeof(g_cubtmp);
    cub::DeviceScan::ExclusiveSum(p_tmp, tb, (const int*)p_fidx, (int*)p_rank, n, 0);

    tb = sizeof(g_cubtmp);
    cub::DeviceScan::InclusiveScan(p_tmp, tb, (const int*)p_w, (int*)p_hp,
                                   MaxOp(), n, 0);

    passS2<<<nb, 256>>>(pts, vs, cr, n, out);
    passT<<<(MAXV + 255) / 256, 256>>>(out, n);
}

// round 13
// speedup vs baseline: 1.1381x; 1.1381x over previous
#include <cuda_runtime.h>
#include <cub/cub.cuh>
#include <cstdint>

#define MAXP 10
#define MAXV 160000
#define NCAP (1 << 21)
#define IDX_BITS 21
#define IDX_MASK ((1u << IDX_BITS) - 1u)
#define BBITS 21
#define NBUCKET (1u << BBITS)
#define BSHIFT (32 - BBITS)   // 11: bucket = flipped_key >> 11

// Output layout (tuple order): voxels | coors | num_points | voxel_num
#define OFF_VOX   0
#define OFF_COORS 8000000
#define OFF_CNT   8480000
#define OFF_VNUM  8640000
#define OUT_ELEMS 8640001

// ---- device scratch (static globals: allowed; no runtime allocation) ----
__device__ unsigned long long g_val[NCAP];      // per-point (lin << 21 | idx)
__device__ unsigned long long g_sorted[NCAP];   // bucket-sorted, then locally sorted
__device__ int g_bcnt[NBUCKET];                 // bucket histogram (zeroed per run)
__device__ int g_boff[NBUCKET];                 // exclusive offsets; mutated to ENDS by scatter
__device__ int g_fidx[NCAP];                    // head flag in ORIGINAL index order
__device__ int g_rank[NCAP];                    // exclusive prefix sum of g_fidx
__device__ int g_cnt[MAXV];
__device__ __align__(256) unsigned char g_cubtmp[4u << 20];

// Flipped (sign-bit-toggled) wrapped int32 key: unsigned order == signed order.
__device__ __forceinline__ unsigned fkey_of(unsigned long long v, unsigned n) {
    return ((unsigned)(v >> IDX_BITS) * n + (unsigned)(v & IDX_MASK)) ^ 0x80000000u;
}

// IEEE f32 quantization (bit-matches XLA CPU float32; immune to fast-math).
__device__ __forceinline__ void grid_dims(const float* __restrict__ vs,
                                          const float* __restrict__ cr,
                                          int& gx, int& gy, int& gz) {
    gx = (int)rintf(__fdiv_rn(__fsub_rn(cr[3], cr[0]), vs[0]));
    gy = (int)rintf(__fdiv_rn(__fsub_rn(cr[4], cr[1]), vs[1]));
    gz = (int)rintf(__fdiv_rn(__fsub_rn(cr[5], cr[2]), vs[2]));
}

// Pass K: quantize; histogram buckets of the flipped wrapped key; stash payload.
__global__ void passK(const float* __restrict__ pts, const float* __restrict__ vs,
                      const float* __restrict__ cr, int n) {
    int i = blockIdx.x * 256 + threadIdx.x;
    if (i >= n) return;
    int gx, gy, gz;
    grid_dims(vs, cr, gx, gy, gz);
    float m0 = cr[0], m1 = cr[1], m2 = cr[2];
    size_t b = (size_t)i * 5;
    float px = pts[b + 0], py = pts[b + 1], pz = pts[b + 2];
    int cx = (int)floorf(__fdiv_rn(__fsub_rn(px, m0), vs[0]));
    int cy = (int)floorf(__fdiv_rn(__fsub_rn(py, m1), vs[1]));
    int cz = (int)floorf(__fdiv_rn(__fsub_rn(pz, m2), vs[2]));
    bool valid = (cx >= 0) && (cx < gx) && (cy >= 0) && (cy < gy) &&
                 (cz >= 0) && (cz < gz);
    int total = gx * gy * gz;                        // 82,944,000 fits int32
    int lin = valid ? ((cx * gy + cy) * gz + cz) : total;
    unsigned fk = ((unsigned)lin * (unsigned)n + (unsigned)i) ^ 0x80000000u;
    atomicAdd(&g_bcnt[fk >> BSHIFT], 1);
    g_val[i] = ((unsigned long long)(unsigned)lin << IDX_BITS) | (unsigned)i;
}

// Pass SC: scatter each point into its bucket region (intra-bucket order arbitrary;
// fixed deterministically by passLS). Mutates g_boff[b] into bucket END offsets.
__global__ void passSC(int n) {
    int i = blockIdx.x * 256 + threadIdx.x;
    if (i >= n) return;
    unsigned long long v = g_val[i];
    unsigned fk = fkey_of(v, (unsigned)n);
    int pos = atomicAdd(&g_boff[fk >> BSHIFT], 1);
    g_sorted[pos] = v;
}

// Pass LS: per-bucket insertion sort by (flipped key, idx). After this the whole
// g_sorted array is in exact (signed wrapped key, original index) order ==
// jnp.argsort(lin*N+idx) with stable tie-break.
__global__ void passLS(int n) {
    unsigned b = blockIdx.x * 256 + threadIdx.x;
    if (b >= NBUCKET) return;
    int end = g_boff[b];                  // mutated = exclusive end of bucket b
    int start = (b == 0) ? 0 : g_boff[b - 1];
    if (end - start < 2) return;          // ~89% of non-empty buckets
    unsigned un = (unsigned)n;
    for (int a = start + 1; a < end; a++) {
        unsigned long long v = g_sorted[a];
        unsigned kv = fkey_of(v, un);
        unsigned iv = (unsigned)(v & IDX_MASK);
        int c = a - 1;
        while (c >= start) {
            unsigned long long w = g_sorted[c];
            unsigned kw = fkey_of(w, un);
            if (kw > kv || (kw == kv && (unsigned)(w & IDX_MASK) > iv)) {
                g_sorted[c + 1] = w;
                c--;
            } else break;
        }
        g_sorted[c + 1] = v;
    }
}

// Pass S1 (sorted order): is_head = valid && lin != prev lin; scatter to idx order.
__global__ void passS1(const float* __restrict__ vs, const float* __restrict__ cr, int n) {
    int p = blockIdx.x * 256 + threadIdx.x;
    if (p >= n) return;
    int gx, gy, gz;
    grid_dims(vs, cr, gx, gy, gz);
    int total = gx * gy * gz;
    unsigned long long v = g_sorted[p];
    int lin  = (int)(v >> IDX_BITS);
    int linp = (p > 0) ? (int)(g_sorted[p - 1] >> IDX_BITS) : -1;
    g_fidx[(unsigned)(v & IDX_MASK)] = (lin < total) && (lin != linp);
}

// Pass S2 (sorted order): backward-walk to run head (runs are tiny); slot = p-h;
// vox = rank of head's original index among heads; scatter outputs.
__global__ void passS2(const float* __restrict__ pts, const float* __restrict__ vs,
                       const float* __restrict__ cr, int n, float* __restrict__ out) {
    int p = blockIdx.x * 256 + threadIdx.x;
    if (p >= n) return;
    int gx, gy, gz;
    grid_dims(vs, cr, gx, gy, gz);
    int total = gx * gy * gz;
    unsigned long long v = g_sorted[p];
    int lin = (int)(v >> IDX_BITS);
    if (lin >= total) return;                 // invalid point
    int h = p;                                // walk back to run head
    while (h > 0 && (int)(g_sorted[h - 1] >> IDX_BITS) == lin) h--;
    int slot = p - h;
    int head_orig = (int)(g_sorted[h] & IDX_MASK);
    int vox = g_rank[head_orig];
    if (vox >= MAXV) return;
    atomicAdd(&g_cnt[vox], 1);
    if (slot < MAXP) {
        int o = (int)(v & IDX_MASK);
        const float* src = pts + (size_t)o * 5;
        float* dst = out + OFF_VOX + (size_t)vox * (MAXP * 5) + slot * 5;
        dst[0] = src[0]; dst[1] = src[1]; dst[2] = src[2];
        dst[3] = src[3]; dst[4] = src[4];
    }
    if (p == h) {                             // head writes coors (z, y, x)
        int cz = lin % gz;
        int r = lin / gz;
        int cy = r % gy;
        int cx = r / gy;
        float* oc = out + OFF_COORS + (size_t)vox * 3;
        oc[0] = (float)cz;
        oc[1] = (float)cy;
        oc[2] = (float)cx;
    }
}

// Pass T: counts -> min(cnt,10) as float, voxel_num scalar.
__global__ void passT(float* __restrict__ out, int n) {
    int v = blockIdx.x * blockDim.x + threadIdx.x;
    if (v < MAXV) out[OFF_CNT + v] = (float)min(g_cnt[v], MAXP);
    if (v == 0) {
        int H = g_rank[n - 1] + g_fidx[n - 1];
        out[OFF_VNUM] = (float)min(H, MAXV);
    }
}

extern "C" void kernel_launch(void* const* d_in, const int* in_sizes, int n_in,
                              void* d_out, int out_size) {
    // Disambiguate inputs by element count: points = largest,
    // voxel_size = 3 elements, coors_range = 6 elements.
    const float* pts = nullptr;
    const float* vs  = nullptr;
    const float* cr  = nullptr;
    int pts_size = -1;
    for (int k = 0; k < n_in; k++) {
        int sz = in_sizes[k];
        if (sz == 3) vs = (const float*)d_in[k];
        else if (sz == 6) cr = (const float*)d_in[k];
        if (sz > pts_size) { pts_size = sz; pts = (const float*)d_in[k]; }
    }
    int n = pts_size / 5;
    float* out = (float*)d_out;

    void *p_bcnt, *p_boff, *p_fidx, *p_rank, *p_cnt, *p_tmp;
    cudaGetSymbolAddress(&p_bcnt, g_bcnt);
    cudaGetSymbolAddress(&p_boff, g_boff);
    cudaGetSymbolAddress(&p_fidx, g_fidx);
    cudaGetSymbolAddress(&p_rank, g_rank);
    cudaGetSymbolAddress(&p_cnt, g_cnt);
    cudaGetSymbolAddress(&p_tmp, g_cubtmp);

    cudaMemsetAsync(out, 0, (size_t)OUT_ELEMS * sizeof(float), 0);
    cudaMemsetAsync(p_bcnt, 0, sizeof(int) * NBUCKET, 0);
    cudaMemsetAsync(p_cnt, 0, sizeof(int) * MAXV, 0);

    int nb = (n + 255) / 256;
    passK<<<nb, 256>>>(pts, vs, cr, n);

    size_t tb = sizeof(g_cubtmp);
    cub::DeviceScan::ExclusiveSum(p_tmp, tb, (const int*)p_bcnt,
                                  (int*)p_boff, (int)NBUCKET, 0);

    passSC<<<nb, 256>>>(n);
    passLS<<<(NBUCKET + 255) / 256, 256>>>(n);
    passS1<<<nb, 256>>>(vs, cr, n);

    tb = sizeof(g_cubtmp);
    cub::DeviceScan::ExclusiveSum(p_tmp, tb, (const int*)p_fidx,
                                  (int*)p_rank, n, 0);

    passS2<<<nb, 256>>>(pts, vs, cr, n, out);
    passT<<<(MAXV + 255) / 256, 256>>>(out, n);
}